// round 2
// baseline (speedup 1.0000x reference)
#include <cuda_runtime.h>
#include <math_constants.h>

#define HH 512
#define WW 1024
#define NPIX (HH * WW)      // 524288 = 2^19
#define KNB 15
#define GAMMA_F 0.1f

#define P2_BLOCK 256
#define P2_GRID  (NPIX / P2_BLOCK)   // 2048

// Packed per-pixel data, 32 bytes, 32B-aligned:
//   [2*i+0] = (px, py, pz, pn)
//   [2*i+1] = (nx, ny, nz, 0)
__device__ float4 g_packed[2 * NPIX];
__device__ float  g_partials[P2_GRID];

// ---------------- Pass 1: pack p, n, pn per pixel ----------------
__global__ void __launch_bounds__(256) pack_kernel(const float* __restrict__ sig1,
                                                   const float* __restrict__ sig2) {
    int i = blockIdx.x * 256 + threadIdx.x;
    int row = i >> 10;          // W = 1024
    int col = i & 1023;

    float lat = (0.5f - (row + 0.5f) * (1.0f / HH)) * CUDART_PI_F;
    float lon = ((col + 0.5f) * (1.0f / WW) - 0.5f) * (2.0f * CUDART_PI_F);
    float sla, cla, slo, clo;
    sincosf(lat, &sla, &cla);
    sincosf(lon, &slo, &clo);

    float s  = sig1[i];
    float px = s * cla * slo;
    float py = s * sla;
    float pz = s * cla * clo;

    float nx = sig2[i];
    float ny = sig2[NPIX + i];
    float nz = sig2[2 * NPIX + i];

    float pn = px * nx + py * ny + pz * nz;

    g_packed[2 * i + 0] = make_float4(px, py, pz, pn);
    g_packed[2 * i + 1] = make_float4(nx, ny, nz, 0.0f);
}

// ---------------- Pass 2: per-pixel loss, per-block partial ----------------
__global__ void __launch_bounds__(P2_BLOCK) loss_kernel(const float* __restrict__ weights,
                                                        const int* __restrict__ nb) {
    int i = blockIdx.x * P2_BLOCK + threadIdx.x;

    // Own pixel data (coalesced, one 32B sector per thread)
    float4 P  = g_packed[2 * i + 0];
    float4 Nv = g_packed[2 * i + 1];
    float pn_i = P.w;

    float acc1 = 0.0f;   // sum_k (aux1*w)^2
    float acc2 = 0.0f;   // sum_k aux2*w

#pragma unroll
    for (int k = 0; k < KNB; k++) {
        // Streaming reads: evict-first so the packed array stays L2-resident
        int   j = __ldcs(&nb[k * NPIX + i]) & (NPIX - 1);
        float w = __ldcs(&weights[k * NPIX + i]);

        // One 32B sector gather per neighbour (mostly L2 hits)
        float4 Pj = __ldg(&g_packed[2 * j + 0]);
        float4 Nj = __ldg(&g_packed[2 * j + 1]);

        float aux1 = pn_i - (Pj.x * Nv.x + Pj.y * Nv.y + Pj.z * Nv.z);
        float dx = Nv.x - Nj.x;
        float dy = Nv.y - Nj.y;
        float dz = Nv.z - Nj.z;
        float aux2 = sqrtf(dx * dx + dy * dy + dz * dz);

        float t = aux1 * w;
        acc1 += t * t;
        acc2 += aux2 * w;
    }

    float v = sqrtf(acc1) + GAMMA_F * acc2;

    // Deterministic block tree-reduce
    __shared__ float sm[P2_BLOCK];
    sm[threadIdx.x] = v;
    __syncthreads();
#pragma unroll
    for (int s = P2_BLOCK / 2; s > 0; s >>= 1) {
        if (threadIdx.x < s) sm[threadIdx.x] += sm[threadIdx.x + s];
        __syncthreads();
    }
    if (threadIdx.x == 0) g_partials[blockIdx.x] = sm[0];
}

// ---------------- Pass 3: deterministic final reduce ----------------
__global__ void __launch_bounds__(1024) finalize_kernel(float* __restrict__ out) {
    __shared__ float sm[1024];
    float v = 0.0f;
#pragma unroll
    for (int idx = threadIdx.x; idx < P2_GRID; idx += 1024)
        v += g_partials[idx];
    sm[threadIdx.x] = v;
    __syncthreads();
#pragma unroll
    for (int s = 512; s > 0; s >>= 1) {
        if (threadIdx.x < s) sm[threadIdx.x] += sm[threadIdx.x + s];
        __syncthreads();
    }
    if (threadIdx.x == 0)
        out[0] = sm[0] * (1.0f / (float)NPIX);   // MULTIPLIER = 1.0
}

extern "C" void kernel_launch(void* const* d_in, const int* in_sizes, int n_in,
                              void* d_out, int out_size) {
    const float* sig1    = (const float*)d_in[0];   // N f32
    const float* sig2    = (const float*)d_in[1];   // 3N f32
    const float* weights = (const float*)d_in[2];   // K*N f32
    const int*   nb      = (const int*)d_in[3];     // K*N int32 (JAX x64 disabled)
    float* out = (float*)d_out;

    pack_kernel<<<NPIX / 256, 256>>>(sig1, sig2);
    loss_kernel<<<P2_GRID, P2_BLOCK>>>(weights, nb);
    finalize_kernel<<<1, 1024>>>(out);
}

// round 3
// speedup vs baseline: 1.3888x; 1.3888x over previous
#include <cuda_runtime.h>
#include <math_constants.h>

#define HH 512
#define WW 1024
#define NPIX (HH * WW)      // 524288 = 2^19
#define KNB 15
#define GAMMA_F 0.1f

#define P2_BLOCK 256
#define P2_GRID  (NPIX / P2_BLOCK)   // 2048

// Packed per-pixel data, 16 bytes: (s, nx, ny, nz).
// p is reconstructed as s * dir(index), dir computed analytically.
__device__ float4 g_packed[NPIX];
__device__ float  g_partials[P2_GRID];

// Direction from pixel index (ERP grid), fast intrinsics.
__device__ __forceinline__ void erp_dir(int i, float& dx, float& dy, float& dz) {
    int row = i >> 10;          // W = 1024
    int col = i & 1023;
    float lat = 0.5f * CUDART_PI_F - (row + 0.5f) * (CUDART_PI_F / HH);
    float lon = (col + 0.5f) * (2.0f * CUDART_PI_F / WW) - CUDART_PI_F;
    float sla = __sinf(lat), cla = __cosf(lat);
    float slo = __sinf(lon), clo = __cosf(lon);
    dx = cla * slo;
    dy = sla;
    dz = cla * clo;
}

// ---------------- Pass 1: pure interleave {s, nx, ny, nz} ----------------
__global__ void __launch_bounds__(256) pack_kernel(const float* __restrict__ sig1,
                                                   const float* __restrict__ sig2) {
    int i = blockIdx.x * 256 + threadIdx.x;
    float s  = sig1[i];
    float nx = sig2[i];
    float ny = sig2[NPIX + i];
    float nz = sig2[2 * NPIX + i];
    g_packed[i] = make_float4(s, nx, ny, nz);
}

// ---------------- Pass 2: per-pixel loss, per-block partial ----------------
__global__ void __launch_bounds__(P2_BLOCK) loss_kernel(const float* __restrict__ weights,
                                                        const int* __restrict__ nb) {
    int i = blockIdx.x * P2_BLOCK + threadIdx.x;

    // Own pixel (coalesced 16B load + analytic direction)
    float4 E = g_packed[i];
    float dix, diy, diz;
    erp_dir(i, dix, diy, diz);
    float nix = E.y, niy = E.z, niz = E.w;
    float pn_i = E.x * (dix * nix + diy * niy + diz * niz);

    float acc1 = 0.0f;   // sum_k (aux1*w)^2
    float acc2 = 0.0f;   // sum_k aux2*w

#pragma unroll
    for (int k = 0; k < KNB; k++) {
        // Streaming reads (evict-first: keep packed array L2-resident)
        int   j = __ldcs(&nb[k * NPIX + i]) & (NPIX - 1);
        float w = __ldcs(&weights[k * NPIX + i]);

        // ONE 16B gather per neighbour (single LDG.128, ~32 wavefronts/warp)
        float4 Ej = __ldg(&g_packed[j]);

        float djx, djy, djz;
        erp_dir(j, djx, djy, djz);

        // dot(p_j, n_i) = s_j * dot(dir_j, n_i)
        float dotpn = Ej.x * (djx * nix + djy * niy + djz * niz);
        float aux1 = pn_i - dotpn;

        float ddx = nix - Ej.y;
        float ddy = niy - Ej.z;
        float ddz = niz - Ej.w;
        float aux2 = sqrtf(ddx * ddx + ddy * ddy + ddz * ddz);

        float t = aux1 * w;
        acc1 += t * t;
        acc2 += aux2 * w;
    }

    float v = sqrtf(acc1) + GAMMA_F * acc2;

    // Deterministic block tree-reduce
    __shared__ float sm[P2_BLOCK];
    sm[threadIdx.x] = v;
    __syncthreads();
#pragma unroll
    for (int s = P2_BLOCK / 2; s > 0; s >>= 1) {
        if (threadIdx.x < s) sm[threadIdx.x] += sm[threadIdx.x + s];
        __syncthreads();
    }
    if (threadIdx.x == 0) g_partials[blockIdx.x] = sm[0];
}

// ---------------- Pass 3: deterministic final reduce ----------------
__global__ void __launch_bounds__(1024) finalize_kernel(float* __restrict__ out) {
    __shared__ float sm[1024];
    float v = 0.0f;
#pragma unroll
    for (int idx = threadIdx.x; idx < P2_GRID; idx += 1024)
        v += g_partials[idx];
    sm[threadIdx.x] = v;
    __syncthreads();
#pragma unroll
    for (int s = 512; s > 0; s >>= 1) {
        if (threadIdx.x < s) sm[threadIdx.x] += sm[threadIdx.x + s];
        __syncthreads();
    }
    if (threadIdx.x == 0)
        out[0] = sm[0] * (1.0f / (float)NPIX);   // MULTIPLIER = 1.0
}

extern "C" void kernel_launch(void* const* d_in, const int* in_sizes, int n_in,
                              void* d_out, int out_size) {
    const float* sig1    = (const float*)d_in[0];   // N f32
    const float* sig2    = (const float*)d_in[1];   // 3N f32
    const float* weights = (const float*)d_in[2];   // K*N f32
    const int*   nb      = (const int*)d_in[3];     // K*N int32
    float* out = (float*)d_out;

    pack_kernel<<<NPIX / 256, 256>>>(sig1, sig2);
    loss_kernel<<<P2_GRID, P2_BLOCK>>>(weights, nb);
    finalize_kernel<<<1, 1024>>>(out);
}